// round 12
// baseline (speedup 1.0000x reference)
#include <cuda_runtime.h>
#include <cuda_bf16.h>
#include <stdint.h>
#include <string.h>

#define N_NODES 50000
#define N_EDGES 800000
#define COLCAP (N_EDGES + 4 * N_NODES + 64)   // padded colidx capacity

// ---------------- PDL primitives (sm_90+) ------------------------------------
#define PDL_TRIGGER() asm volatile("griddepcontrol.launch_dependents;" ::: "memory")
#define PDL_WAIT()    asm volatile("griddepcontrol.wait;" ::: "memory")

// ---------------- scratch (device globals; zero-initialized at load) --------
// invariant: g_deg all-zero and g_counter==0 at entry of every run
// (restored by the tail of k_l23 each run)
__device__ int   g_counter;
__device__ int   g_deg[N_NODES];
__device__ int   g_rowptr[N_NODES];      // bucket start (multiple of 4)
__device__ int   g_rowend[N_NODES];      // bucket padded end (multiple of 4)
__device__ int   g_rowcur[N_NODES];      // scatter cursor
__device__ int   g_colidx[COLCAP];
__device__ float g_dis[N_NODES];
// per-stage buffers; gather sources have one extra always-zero row (index N_NODES)
__device__ float g_f16[(N_NODES + 1) * 16];   // dis*x        (gather src 1)
__device__ float g_a16[N_NODES * 16];         // agg16 out
__device__ float g_f32[(N_NODES + 1) * 32];   // conv1 out    (gather src 2)
__device__ float g_a32[N_NODES * 32];         // agg32 out
__device__ float g_f64[(N_NODES + 1) * 64];   // conv2 out    (gather src 3)
__device__ float g_a64[N_NODES * 64];         // agg64 out
__device__ float g_h128[N_NODES * 128];       // conv3 out
__device__ float g_h64[N_NODES * 64];         // dense l1 out

// ---------------- packed f32x2 helpers (Blackwell) ---------------------------
__device__ __forceinline__ unsigned long long pack2(float x, float y) {
    unsigned long long r;
    asm("mov.b64 %0, {%1, %2};" : "=l"(r) : "f"(x), "f"(y));
    return r;
}
__device__ __forceinline__ void unpack2(unsigned long long v, float& x, float& y) {
    asm("mov.b64 {%0, %1}, %2;" : "=f"(x), "=f"(y) : "l"(v));
}
__device__ __forceinline__ unsigned long long fma2(unsigned long long a,
                                                   unsigned long long b,
                                                   unsigned long long c) {
    unsigned long long d;
    asm("fma.rn.f32x2 %0, %1, %2, %3;" : "=l"(d) : "l"(a), "l"(b), "l"(c));
    return d;
}

// per-block edge-dtype probe (reads only kernel inputs)
__device__ __forceinline__ int probe_is64(const void* ei) {
    const long long* p = (const long long*)ei;
    int ok64 = 1;
#pragma unroll 8
    for (int q = 0; q < 64; q++) {
        long long v = p[q];
        if (v < 0 || v >= N_NODES) { ok64 = 0; break; }
    }
    return ok64;
}

// load 8 consecutive edge indices starting at element base8*8
__device__ __forceinline__ void load8(const void* ei, int is64, long long off,
                                      int t, int out[8]) {
    if (is64) {
        const longlong2* p = (const longlong2*)ei + off / 2 + (long long)t * 4;
        longlong2 a = __ldg(&p[0]), b = __ldg(&p[1]);
        longlong2 c = __ldg(&p[2]), d = __ldg(&p[3]);
        out[0] = (int)a.x; out[1] = (int)a.y; out[2] = (int)b.x; out[3] = (int)b.y;
        out[4] = (int)c.x; out[5] = (int)c.y; out[6] = (int)d.x; out[7] = (int)d.y;
    } else {
        const int4* p = (const int4*)ei + off / 4 + (long long)t * 2;
        int4 a = __ldg(&p[0]), b = __ldg(&p[1]);
        out[0] = a.x; out[1] = a.y; out[2] = a.z; out[3] = a.w;
        out[4] = b.x; out[5] = b.y; out[6] = b.z; out[7] = b.w;
    }
}

// ---------------- CSR build ---------------------------------------------------
// 8 dst indices per thread (MLP-8 atomics)
__global__ void k_hist(const void* __restrict__ ei) {
    PDL_TRIGGER();
    __shared__ int s_is64;
    if (threadIdx.x == 0) s_is64 = probe_is64(ei);
    __syncthreads();
    int t = blockIdx.x * blockDim.x + threadIdx.x;
    if (t >= N_EDGES / 8) return;
    int d[8];
    load8(ei, s_is64, N_EDGES, t, d);
#pragma unroll
    for (int q = 0; q < 8; q++)
        if (d[q] >= 0 && d[q] < N_NODES) atomicAdd(&g_deg[d[q]], 1);
}

// bucket bases (padded to multiples of 4): block scan + one atomic per block
__global__ void k_base() {
    PDL_TRIGGER();
    PDL_WAIT();                       // needs g_deg complete
    __shared__ int ws[9];
    int i = blockIdx.x * blockDim.x + threadIdx.x;
    int d    = (i < N_NODES) ? g_deg[i] : 0;
    int degp = (d + 3) & ~3;
    int lane = threadIdx.x & 31, w = threadIdx.x >> 5;
    int incl = degp;
#pragma unroll
    for (int off = 1; off < 32; off <<= 1) {
        int t = __shfl_up_sync(0xffffffffu, incl, off);
        if (lane >= off) incl += t;
    }
    if (lane == 31) ws[w] = incl;
    __syncthreads();
    if (threadIdx.x == 0) {
        int r = 0;
#pragma unroll
        for (int j = 0; j < 8; j++) { int t = ws[j]; ws[j] = r; r += t; }
        ws[8] = atomicAdd(&g_counter, r);   // block base
    }
    __syncthreads();
    int base = ws[8] + ws[w] + incl - degp;
    if (i < N_NODES) {
        g_rowptr[i] = base;
        g_rowcur[i] = base;
        g_rowend[i] = base + degp;
        g_dis[i]    = rsqrtf((float)(d + 1));
        for (int q = d; q < degp; q++) g_colidx[base + q] = N_NODES;
    }
}

// scatter 8 edges per thread + scale one float4 of layer-1 input.
// Edge + x loads (pure inputs) run BEFORE the PDL wait -> overlap with k_base.
__global__ void k_scatter(const void* __restrict__ ei,
                          const float4* __restrict__ x, float4* __restrict__ f) {
    PDL_TRIGGER();
    __shared__ int s_is64;
    if (threadIdx.x == 0) s_is64 = probe_is64(ei);
    __syncthreads();
    int t = blockIdx.x * blockDim.x + threadIdx.x;

    int s[8], d[8];
    bool haveEdges = (t < N_EDGES / 8);
    if (haveEdges) {
        load8(ei, s_is64, 0, t, s);
        load8(ei, s_is64, N_EDGES, t, d);
    }
    float4 xv = make_float4(0.f, 0.f, 0.f, 0.f);
    bool haveX = (t < N_NODES * 4);
    if (haveX) xv = __ldg(&x[t]);

    PDL_WAIT();                       // needs g_rowcur / g_dis

    if (haveEdges) {
#pragma unroll
        for (int q = 0; q < 8; q++) {
            if (d[q] >= 0 && d[q] < N_NODES) {
                int src = (s[q] >= 0 && s[q] < N_NODES) ? s[q] : N_NODES;
                int p = atomicAdd(&g_rowcur[d[q]], 1);
                g_colidx[p] = src;
            }
        }
    }
    if (haveX) {
        float dd = g_dis[t >> 2];
        xv.x *= dd; xv.y *= dd; xv.z *= dd; xv.w *= dd;
        f[t] = xv;
    }
}

// ---------------- aggregation kernels (unroll-16, int4 index loads) ----------
__global__ void k_agg16(const float* __restrict__ g, float* __restrict__ agg) {
    PDL_TRIGGER();
    int t = blockIdx.x * blockDim.x + threadIdx.x;
    int node = t >> 4;
    int lane = t & 15;
    PDL_WAIT();
    if (node >= N_NODES) return;

    float acc = __ldg(&g[node * 16 + lane]);
    int p   = g_rowptr[node];
    int end = g_rowend[node];
    while (p + 16 <= end) {
        int4 i0 = __ldg((const int4*)&g_colidx[p]);
        int4 i1 = __ldg((const int4*)&g_colidx[p + 4]);
        int4 i2 = __ldg((const int4*)&g_colidx[p + 8]);
        int4 i3 = __ldg((const int4*)&g_colidx[p + 12]);
        float v0 = __ldg(&g[i0.x * 16 + lane]);
        float v1 = __ldg(&g[i0.y * 16 + lane]);
        float v2 = __ldg(&g[i0.z * 16 + lane]);
        float v3 = __ldg(&g[i0.w * 16 + lane]);
        float v4 = __ldg(&g[i1.x * 16 + lane]);
        float v5 = __ldg(&g[i1.y * 16 + lane]);
        float v6 = __ldg(&g[i1.z * 16 + lane]);
        float v7 = __ldg(&g[i1.w * 16 + lane]);
        float v8 = __ldg(&g[i2.x * 16 + lane]);
        float v9 = __ldg(&g[i2.y * 16 + lane]);
        float va = __ldg(&g[i2.z * 16 + lane]);
        float vb = __ldg(&g[i2.w * 16 + lane]);
        float vc = __ldg(&g[i3.x * 16 + lane]);
        float vd = __ldg(&g[i3.y * 16 + lane]);
        float ve = __ldg(&g[i3.z * 16 + lane]);
        float vf = __ldg(&g[i3.w * 16 + lane]);
        acc += ((v0 + v1) + (v2 + v3)) + ((v4 + v5) + (v6 + v7))
             + ((v8 + v9) + (va + vb)) + ((vc + vd) + (ve + vf));
        p += 16;
    }
    while (p + 4 <= end) {
        int4 a = __ldg((const int4*)&g_colidx[p]);
        acc += __ldg(&g[a.x * 16 + lane]);
        acc += __ldg(&g[a.y * 16 + lane]);
        acc += __ldg(&g[a.z * 16 + lane]);
        acc += __ldg(&g[a.w * 16 + lane]);
        p += 4;
    }
    agg[node * 16 + lane] = acc * g_dis[node];
}

__global__ void k_agg32(const float* __restrict__ g, float* __restrict__ agg) {
    PDL_TRIGGER();
    int warp = (blockIdx.x * blockDim.x + threadIdx.x) >> 5;
    int lane = threadIdx.x & 31;
    PDL_WAIT();
    if (warp >= N_NODES) return;

    float acc = __ldg(&g[warp * 32 + lane]);
    int p   = g_rowptr[warp];
    int end = g_rowend[warp];
    while (p + 16 <= end) {
        int4 i0 = __ldg((const int4*)&g_colidx[p]);
        int4 i1 = __ldg((const int4*)&g_colidx[p + 4]);
        int4 i2 = __ldg((const int4*)&g_colidx[p + 8]);
        int4 i3 = __ldg((const int4*)&g_colidx[p + 12]);
        float v0 = __ldg(&g[(size_t)i0.x * 32 + lane]);
        float v1 = __ldg(&g[(size_t)i0.y * 32 + lane]);
        float v2 = __ldg(&g[(size_t)i0.z * 32 + lane]);
        float v3 = __ldg(&g[(size_t)i0.w * 32 + lane]);
        float v4 = __ldg(&g[(size_t)i1.x * 32 + lane]);
        float v5 = __ldg(&g[(size_t)i1.y * 32 + lane]);
        float v6 = __ldg(&g[(size_t)i1.z * 32 + lane]);
        float v7 = __ldg(&g[(size_t)i1.w * 32 + lane]);
        float v8 = __ldg(&g[(size_t)i2.x * 32 + lane]);
        float v9 = __ldg(&g[(size_t)i2.y * 32 + lane]);
        float va = __ldg(&g[(size_t)i2.z * 32 + lane]);
        float vb = __ldg(&g[(size_t)i2.w * 32 + lane]);
        float vc = __ldg(&g[(size_t)i3.x * 32 + lane]);
        float vd = __ldg(&g[(size_t)i3.y * 32 + lane]);
        float ve = __ldg(&g[(size_t)i3.z * 32 + lane]);
        float vf = __ldg(&g[(size_t)i3.w * 32 + lane]);
        acc += ((v0 + v1) + (v2 + v3)) + ((v4 + v5) + (v6 + v7))
             + ((v8 + v9) + (va + vb)) + ((vc + vd) + (ve + vf));
        p += 16;
    }
    while (p + 4 <= end) {
        int4 a = __ldg((const int4*)&g_colidx[p]);
        acc += __ldg(&g[(size_t)a.x * 32 + lane]);
        acc += __ldg(&g[(size_t)a.y * 32 + lane]);
        acc += __ldg(&g[(size_t)a.z * 32 + lane]);
        acc += __ldg(&g[(size_t)a.w * 32 + lane]);
        p += 4;
    }
    agg[warp * 32 + lane] = acc * g_dis[warp];
}

__global__ void k_agg64(const float* __restrict__ g, float* __restrict__ agg) {
    PDL_TRIGGER();
    int warp = (blockIdx.x * blockDim.x + threadIdx.x) >> 5;
    int lane = threadIdx.x & 31;
    PDL_WAIT();
    if (warp >= N_NODES) return;

    const float2* g2 = (const float2*)g;
    float2 acc = __ldg(&g2[(size_t)warp * 32 + lane]);
    int p   = g_rowptr[warp];
    int end = g_rowend[warp];
    while (p + 16 <= end) {
        int4 i0 = __ldg((const int4*)&g_colidx[p]);
        int4 i1 = __ldg((const int4*)&g_colidx[p + 4]);
        int4 i2 = __ldg((const int4*)&g_colidx[p + 8]);
        int4 i3 = __ldg((const int4*)&g_colidx[p + 12]);
        float2 v0 = __ldg(&g2[(size_t)i0.x * 32 + lane]);
        float2 v1 = __ldg(&g2[(size_t)i0.y * 32 + lane]);
        float2 v2 = __ldg(&g2[(size_t)i0.z * 32 + lane]);
        float2 v3 = __ldg(&g2[(size_t)i0.w * 32 + lane]);
        float2 v4 = __ldg(&g2[(size_t)i1.x * 32 + lane]);
        float2 v5 = __ldg(&g2[(size_t)i1.y * 32 + lane]);
        float2 v6 = __ldg(&g2[(size_t)i1.z * 32 + lane]);
        float2 v7 = __ldg(&g2[(size_t)i1.w * 32 + lane]);
        float2 v8 = __ldg(&g2[(size_t)i2.x * 32 + lane]);
        float2 v9 = __ldg(&g2[(size_t)i2.y * 32 + lane]);
        float2 va = __ldg(&g2[(size_t)i2.z * 32 + lane]);
        float2 vb = __ldg(&g2[(size_t)i2.w * 32 + lane]);
        float2 vc = __ldg(&g2[(size_t)i3.x * 32 + lane]);
        float2 vd = __ldg(&g2[(size_t)i3.y * 32 + lane]);
        float2 ve = __ldg(&g2[(size_t)i3.z * 32 + lane]);
        float2 vf = __ldg(&g2[(size_t)i3.w * 32 + lane]);
        acc.x += ((v0.x + v1.x) + (v2.x + v3.x)) + ((v4.x + v5.x) + (v6.x + v7.x))
               + ((v8.x + v9.x) + (va.x + vb.x)) + ((vc.x + vd.x) + (ve.x + vf.x));
        acc.y += ((v0.y + v1.y) + (v2.y + v3.y)) + ((v4.y + v5.y) + (v6.y + v7.y))
               + ((v8.y + v9.y) + (va.y + vb.y)) + ((vc.y + vd.y) + (ve.y + vf.y));
        p += 16;
    }
    while (p + 4 <= end) {
        int4 ia = __ldg((const int4*)&g_colidx[p]);
        float2 v0 = __ldg(&g2[(size_t)ia.x * 32 + lane]);
        float2 v1 = __ldg(&g2[(size_t)ia.y * 32 + lane]);
        float2 v2 = __ldg(&g2[(size_t)ia.z * 32 + lane]);
        float2 v3 = __ldg(&g2[(size_t)ia.w * 32 + lane]);
        acc.x += (v0.x + v1.x) + (v2.x + v3.x);
        acc.y += (v0.y + v1.y) + (v2.y + v3.y);
        p += 4;
    }
    float dd = g_dis[warp];
    float2 o; o.x = acc.x * dd; o.y = acc.y * dd;
    ((float2*)agg)[(size_t)warp * 32 + lane] = o;
}

// ---------------- register-tiled GEMM + bias + relu (+dis) ------------------
// weights/bias staged BEFORE PDL wait (pure inputs) -> overlap predecessor tail
template <int DIN, int DOUT, bool SCALE>
__global__ void __launch_bounds__(256) k_gemm2(
        const float* __restrict__ in,
        const float* __restrict__ W,
        const float* __restrict__ b,
        float* __restrict__ out) {
    PDL_TRIGGER();
    constexpr int NB  = 64;
    constexpr int TN  = (DOUT >= 32) ? 8 : 4;
    constexpr int TX  = DOUT / TN;
    constexpr int TY  = 256 / TX;
    constexpr int TM  = NB / TY;
    constexpr int KC  = (DIN * DOUT >= 8192) ? 32 : DIN;
    constexpr int NKC = DIN / KC;
    constexpr int INP = KC + 4;                    // float4-aligned padded rows
    constexpr int SWW = DOUT + 2 * (DOUT / 32) + 2;

    __shared__ __align__(16) float inS[NB * INP];
    __shared__ __align__(16) float Ws[KC * SWW];

    const int tid  = threadIdx.x;
    const int tx   = tid % TX;
    const int ty   = tid / TX;
    const int node0 = blockIdx.x * NB;

    // ---- pre-wait prologue: bias + weight chunk 0 (inputs only) ----
    float bb[TN];
#pragma unroll
    for (int j = 0; j < TN; j++) bb[j] = __ldg(&b[tx * TN + j]);
    for (int i = tid; i < KC * DOUT / 2; i += 256) {
        int r = i / (DOUT / 2), c = 2 * (i - r * (DOUT / 2));
        float2 wv = __ldg((const float2*)&W[(size_t)r * DOUT + c]);
        *(float2*)&Ws[r * SWW + c + 2 * (c >> 5)] = wv;
    }

    PDL_WAIT();                        // needs `in`

    // ---- input chunk 0 (float4) ----
    for (int i = tid; i < NB * KC / 4; i += 256) {
        int r = i / (KC / 4), c4 = 4 * (i - r * (KC / 4));
        int node = node0 + r;
        float4 v = make_float4(0.f, 0.f, 0.f, 0.f);
        if (node < N_NODES) v = __ldg((const float4*)&in[(size_t)node * DIN + c4]);
        *(float4*)&inS[r * INP + c4] = v;
    }
    __syncthreads();

    unsigned long long acc[TM][TN / 2];
#pragma unroll
    for (int m = 0; m < TM; m++)
#pragma unroll
        for (int j = 0; j < TN / 2; j++) acc[m][j] = 0ull;

    for (int kc = 0; kc < NKC; kc++) {
#pragma unroll
        for (int k = 0; k < KC; k++) {
            unsigned long long a2[TM];
#pragma unroll
            for (int m = 0; m < TM; m++) {
                float a = inS[(ty * TM + m) * INP + k];
                a2[m] = pack2(a, a);
            }
#pragma unroll
            for (int j = 0; j < TN / 2; j++) {
                int c = tx * TN + 2 * j;
                float2 wv = *reinterpret_cast<const float2*>(
                    &Ws[k * SWW + c + 2 * (c >> 5)]);
                unsigned long long w2 = pack2(wv.x, wv.y);
#pragma unroll
                for (int m = 0; m < TM; m++)
                    acc[m][j] = fma2(a2[m], w2, acc[m][j]);
            }
        }
        if (kc + 1 < NKC) {
            const int k0 = (kc + 1) * KC;
            __syncthreads();
            for (int i = tid; i < KC * DOUT / 2; i += 256) {
                int r = i / (DOUT / 2), c = 2 * (i - r * (DOUT / 2));
                float2 wv = __ldg((const float2*)&W[(size_t)(k0 + r) * DOUT + c]);
                *(float2*)&Ws[r * SWW + c + 2 * (c >> 5)] = wv;
            }
            for (int i = tid; i < NB * KC / 4; i += 256) {
                int r = i / (KC / 4), c4 = 4 * (i - r * (KC / 4));
                int node = node0 + r;
                float4 v = make_float4(0.f, 0.f, 0.f, 0.f);
                if (node < N_NODES)
                    v = __ldg((const float4*)&in[(size_t)node * DIN + k0 + c4]);
                *(float4*)&inS[r * INP + c4] = v;
            }
            __syncthreads();
        }
    }

#pragma unroll
    for (int m = 0; m < TM; m++) {
        int node = node0 + ty * TM + m;
        if (node >= N_NODES) continue;
        float sc = SCALE ? g_dis[node] : 1.f;
        float vals[TN];
#pragma unroll
        for (int j = 0; j < TN / 2; j++) {
            float v0, v1;
            unpack2(acc[m][j], v0, v1);
            v0 += bb[2 * j];     v1 += bb[2 * j + 1];
            v0 = v0 > 0.f ? v0 : 0.f;
            v1 = v1 > 0.f ? v1 : 0.f;
            vals[2 * j]     = v0 * sc;
            vals[2 * j + 1] = v1 * sc;
        }
        float4* o = (float4*)(out + (size_t)node * DOUT + tx * TN);
#pragma unroll
        for (int q = 0; q < TN / 4; q++)
            o[q] = make_float4(vals[4 * q], vals[4 * q + 1],
                               vals[4 * q + 2], vals[4 * q + 3]);
    }
}

// ---------------- fused dense l2+l3 + state reset ----------------------------
__global__ void __launch_bounds__(256) k_l23(
        const float* __restrict__ in,
        const float* __restrict__ W2, const float* __restrict__ b2,
        const float* __restrict__ W3, const float* __restrict__ b3,
        float* __restrict__ out) {
    PDL_TRIGGER();
    __shared__ __align__(16) float h1S[64 * 68];
    __shared__ float h2S[64 * 34];
    __shared__ float W2s[64 * 34];
    __shared__ float W3s[32 * 18];
    __shared__ float b2s[32];
    __shared__ float b3s[16];

    const int tid   = threadIdx.x;
    const int node0 = blockIdx.x * 64;

    // ---- pre-wait prologue: dense weights + biases (inputs only) ----
    for (int i = tid; i < 64 * 32; i += 256) {
        int r = i >> 5, c = i & 31;
        W2s[r * 34 + c] = __ldg(&W2[i]);
    }
    for (int i = tid; i < 32 * 16; i += 256) {
        int r = i >> 4, c = i & 15;
        W3s[r * 18 + c] = __ldg(&W3[i]);
    }
    if (tid < 32) b2s[tid] = __ldg(&b2[tid]);
    else if (tid < 48) b3s[tid - 32] = __ldg(&b3[tid - 32]);

    PDL_WAIT();                        // needs `in` (and all upstream complete)

    // restore the zero-state invariant for the next run (safe: upstream done)
    {
        int t = blockIdx.x * blockDim.x + tid;
        int stride = gridDim.x * blockDim.x;
        for (int i = t; i < N_NODES; i += stride) g_deg[i] = 0;
        if (t == 0) g_counter = 0;
    }

    for (int i = tid; i < 64 * 16; i += 256) {
        int r = i >> 4, c4 = (i & 15) * 4;
        int n = node0 + r;
        float4 v = make_float4(0.f, 0.f, 0.f, 0.f);
        if (n < N_NODES) v = __ldg((const float4*)&in[(size_t)n * 64 + c4]);
        *(float4*)&h1S[r * 68 + c4] = v;
    }
    __syncthreads();

    {
        int r  = tid >> 2;
        int c0 = (tid & 3) * 8;
        unsigned long long acc[4] = {0ull, 0ull, 0ull, 0ull};
#pragma unroll
        for (int k = 0; k < 64; k++) {
            float a = h1S[r * 68 + k];
            unsigned long long a2 = pack2(a, a);
#pragma unroll
            for (int j = 0; j < 4; j++) {
                float2 wv = *reinterpret_cast<const float2*>(&W2s[k * 34 + c0 + 2 * j]);
                acc[j] = fma2(a2, pack2(wv.x, wv.y), acc[j]);
            }
        }
#pragma unroll
        for (int j = 0; j < 4; j++) {
            float v0, v1;
            unpack2(acc[j], v0, v1);
            v0 += b2s[c0 + 2 * j];     v1 += b2s[c0 + 2 * j + 1];
            h2S[r * 34 + c0 + 2 * j]     = v0 > 0.f ? v0 : 0.f;
            h2S[r * 34 + c0 + 2 * j + 1] = v1 > 0.f ? v1 : 0.f;
        }
    }
    __syncthreads();

    {
        int r  = tid >> 2;
        int c0 = (tid & 3) * 4;
        unsigned long long acc[2] = {0ull, 0ull};
#pragma unroll
        for (int k = 0; k < 32; k++) {
            float a = h2S[r * 34 + k];
            unsigned long long a2 = pack2(a, a);
#pragma unroll
            for (int j = 0; j < 2; j++) {
                float2 wv = *reinterpret_cast<const float2*>(&W3s[k * 18 + c0 + 2 * j]);
                acc[j] = fma2(a2, pack2(wv.x, wv.y), acc[j]);
            }
        }
        int n = node0 + r;
        if (n < N_NODES) {
            float v[4];
            unpack2(acc[0], v[0], v[1]);
            unpack2(acc[1], v[2], v[3]);
#pragma unroll
            for (int j = 0; j < 4; j++) {
                v[j] += b3s[c0 + j];
                v[j] = v[j] > 0.f ? v[j] : 0.f;
            }
            *(float4*)(out + (size_t)n * 16 + c0) = make_float4(v[0], v[1], v[2], v[3]);
        }
    }
}

// ---------------- PDL launch helper -------------------------------------------
// NOTE: avoids naming the cudaLaunchAttributeValue union member (header-version
// dependent). The PSS attribute payload is a single int (allowedCount) at
// offset 0 of the union; write it generically.
#define PDL_LAUNCH(kernel, grid, block, ...) do {                          \
    cudaLaunchAttribute _a[1];                                             \
    memset(&_a[0], 0, sizeof(_a[0]));                                      \
    _a[0].id = cudaLaunchAttributeProgrammaticStreamSerialization;         \
    *(int*)&_a[0].val = 1;  /* allowedCount = 1 */                         \
    cudaLaunchConfig_t _c = {};                                            \
    _c.gridDim = dim3(grid); _c.blockDim = dim3(block);                    \
    _c.dynamicSmemBytes = 0; _c.stream = 0;                                \
    _c.attrs = _a; _c.numAttrs = 1;                                        \
    cudaLaunchKernelEx(&_c, kernel, ##__VA_ARGS__);                        \
} while (0)

// ---------------- launch ------------------------------------------------------
extern "C" void kernel_launch(void* const* d_in, const int* in_sizes, int n_in,
                              void* d_out, int out_size) {
    const float* x  = (const float*)d_in[0];
    const void*  ei = d_in[1];
    const float *W1 = (const float*)d_in[2],  *b1 = (const float*)d_in[3];
    const float *W2 = (const float*)d_in[4],  *b2 = (const float*)d_in[5];
    const float *W3 = (const float*)d_in[6],  *b3 = (const float*)d_in[7];
    const float *Wl1= (const float*)d_in[8],  *bl1= (const float*)d_in[9];
    const float *Wl2= (const float*)d_in[10], *bl2= (const float*)d_in[11];
    const float *Wl3= (const float*)d_in[12], *bl3= (const float*)d_in[13];
    float* out = (float*)d_out;

    float *f16, *a16, *f32, *a32, *f64, *a64, *h128, *h64;
    cudaGetSymbolAddress((void**)&f16, g_f16);
    cudaGetSymbolAddress((void**)&a16, g_a16);
    cudaGetSymbolAddress((void**)&f32, g_f32);
    cudaGetSymbolAddress((void**)&a32, g_a32);
    cudaGetSymbolAddress((void**)&f64, g_f64);
    cudaGetSymbolAddress((void**)&a64, g_a64);
    cudaGetSymbolAddress((void**)&h128, g_h128);
    cudaGetSymbolAddress((void**)&h64, g_h64);

    const int TB = 256;
    const int nodeBlocks  = (N_NODES + TB - 1) / TB;
    const int edge8Blocks = (N_EDGES / 8 + TB - 1) / TB;
    const int scatBlocks  = ((N_NODES * 4 > N_EDGES / 8 ? N_NODES * 4 : N_EDGES / 8)
                             + TB - 1) / TB;
    const int tileBlocks  = (N_NODES + 63) / 64;
    const int hwBlocks    = (N_NODES * 16 + TB - 1) / TB;
    const int wBlocks     = (N_NODES * 32 + TB - 1) / TB;

    // --- CSR build ---
    k_hist<<<edge8Blocks, TB>>>(ei);
    PDL_LAUNCH(k_base, nodeBlocks, TB);
    PDL_LAUNCH(k_scatter, scatBlocks, TB, ei, (const float4*)x, (float4*)f16);

    // --- conv 1: 16 -> 32 ---
    PDL_LAUNCH(k_agg16, hwBlocks, TB, (const float*)f16, a16);
    PDL_LAUNCH((k_gemm2<16, 32, true>), tileBlocks, TB,
               (const float*)a16, W1, b1, f32);

    // --- conv 2: 32 -> 64 ---
    PDL_LAUNCH(k_agg32, wBlocks, TB, (const float*)f32, a32);
    PDL_LAUNCH((k_gemm2<32, 64, true>), tileBlocks, TB,
               (const float*)a32, W2, b2, f64);

    // --- conv 3: 64 -> 128 ---
    PDL_LAUNCH(k_agg64, wBlocks, TB, (const float*)f64, a64);
    PDL_LAUNCH((k_gemm2<64, 128, false>), tileBlocks, TB,
               (const float*)a64, W3, b3, h128);

    // --- dense layers ---
    PDL_LAUNCH((k_gemm2<128, 64, false>), tileBlocks, TB,
               (const float*)h128, Wl1, bl1, h64);
    PDL_LAUNCH(k_l23, tileBlocks, TB,
               (const float*)h64, Wl2, bl2, Wl3, bl3, out);
}

// round 15
// speedup vs baseline: 1.0126x; 1.0126x over previous
#include <cuda_runtime.h>
#include <cuda_bf16.h>
#include <stdint.h>
#include <string.h>

#define N_NODES 50000
#define N_EDGES 800000
#define COLCAP (N_EDGES + 4 * N_NODES + 64)   // padded colidx capacity

// ---------------- PDL primitives (sm_90+) ------------------------------------
#define PDL_TRIGGER() asm volatile("griddepcontrol.launch_dependents;" ::: "memory")
#define PDL_WAIT()    asm volatile("griddepcontrol.wait;" ::: "memory")

// ---------------- scratch (device globals; zero-initialized at load) --------
// invariant: g_deg all-zero and g_counter==0 at entry of every run
// (restored by the tail of k_l23 each run)
__device__ int   g_counter;
__device__ int   g_deg[N_NODES];
__device__ int   g_rowptr[N_NODES];      // bucket start (multiple of 4)
__device__ int   g_rowend[N_NODES];      // bucket padded end (multiple of 4)
__device__ int   g_rowcur[N_NODES];      // scatter cursor
__device__ int   g_colidx[COLCAP];
__device__ float g_dis[N_NODES];
// per-stage buffers; gather sources have one extra always-zero row (index N_NODES)
__device__ float g_f16[(N_NODES + 1) * 16];   // dis*x        (gather src 1)
__device__ float g_a16[N_NODES * 16];         // agg16 out
__device__ float g_f32[(N_NODES + 1) * 32];   // conv1 out    (gather src 2)
__device__ float g_a32[N_NODES * 32];         // agg32 out
__device__ float g_f64[(N_NODES + 1) * 64];   // conv2 out    (gather src 3)
__device__ float g_a64[N_NODES * 64];         // agg64 out
__device__ float g_h128[N_NODES * 128];       // conv3 out
__device__ float g_h64[N_NODES * 64];         // dense l1 out

// ---------------- packed f32x2 helpers (Blackwell) ---------------------------
__device__ __forceinline__ unsigned long long pack2(float x, float y) {
    unsigned long long r;
    asm("mov.b64 %0, {%1, %2};" : "=l"(r) : "f"(x), "f"(y));
    return r;
}
__device__ __forceinline__ void unpack2(unsigned long long v, float& x, float& y) {
    asm("mov.b64 {%0, %1}, %2;" : "=f"(x), "=f"(y) : "l"(v));
}
__device__ __forceinline__ unsigned long long fma2(unsigned long long a,
                                                   unsigned long long b,
                                                   unsigned long long c) {
    unsigned long long d;
    asm("fma.rn.f32x2 %0, %1, %2, %3;" : "=l"(d) : "l"(a), "l"(b), "l"(c));
    return d;
}

// per-block edge-dtype probe (reads only kernel inputs)
__device__ __forceinline__ int probe_is64(const void* ei) {
    const long long* p = (const long long*)ei;
    int ok64 = 1;
#pragma unroll 8
    for (int q = 0; q < 64; q++) {
        long long v = p[q];
        if (v < 0 || v >= N_NODES) { ok64 = 0; break; }
    }
    return ok64;
}

// ---------------- CSR build ---------------------------------------------------
// 8 dst indices per thread — integer histogram atomics are exactly commutative,
// so the wider form cannot change any result bit.
__global__ void k_hist(const void* __restrict__ ei) {
    PDL_TRIGGER();
    __shared__ int s_is64;
    if (threadIdx.x == 0) s_is64 = probe_is64(ei);
    __syncthreads();
    int t = blockIdx.x * blockDim.x + threadIdx.x;
    if (t >= N_EDGES / 8) return;
    int d[8];
    if (s_is64) {
        const longlong2* p = (const longlong2*)ei + N_EDGES / 2 + (long long)t * 4;
        longlong2 a = __ldg(&p[0]), b = __ldg(&p[1]);
        longlong2 c = __ldg(&p[2]), e = __ldg(&p[3]);
        d[0] = (int)a.x; d[1] = (int)a.y; d[2] = (int)b.x; d[3] = (int)b.y;
        d[4] = (int)c.x; d[5] = (int)c.y; d[6] = (int)e.x; d[7] = (int)e.y;
    } else {
        const int4* p = (const int4*)ei + N_EDGES / 4 + (long long)t * 2;
        int4 a = __ldg(&p[0]), b = __ldg(&p[1]);
        d[0] = a.x; d[1] = a.y; d[2] = a.z; d[3] = a.w;
        d[4] = b.x; d[5] = b.y; d[6] = b.z; d[7] = b.w;
    }
#pragma unroll
    for (int q = 0; q < 8; q++)
        if (d[q] >= 0 && d[q] < N_NODES) atomicAdd(&g_deg[d[q]], 1);
}

// bucket bases (padded to multiples of 4): block scan + one atomic per block.
// Also scales the layer-1 input: f16[i,:] = dis[i]*x[i,:] (x pre-loaded before
// the PDL wait so it overlaps k_hist).
__global__ void k_base(const float4* __restrict__ x, float4* __restrict__ f) {
    PDL_TRIGGER();
    __shared__ int ws[9];
    int i = blockIdx.x * blockDim.x + threadIdx.x;

    // pre-wait prologue: load this node's 16 input features (pure inputs)
    float4 xv[4];
    if (i < N_NODES) {
#pragma unroll
        for (int q = 0; q < 4; q++) xv[q] = __ldg(&x[i * 4 + q]);
    }

    PDL_WAIT();                       // needs g_deg complete

    int d    = (i < N_NODES) ? g_deg[i] : 0;
    int degp = (d + 3) & ~3;
    int lane = threadIdx.x & 31, w = threadIdx.x >> 5;
    int incl = degp;
#pragma unroll
    for (int off = 1; off < 32; off <<= 1) {
        int t = __shfl_up_sync(0xffffffffu, incl, off);
        if (lane >= off) incl += t;
    }
    if (lane == 31) ws[w] = incl;
    __syncthreads();
    if (threadIdx.x == 0) {
        int r = 0;
#pragma unroll
        for (int j = 0; j < 8; j++) { int t = ws[j]; ws[j] = r; r += t; }
        ws[8] = atomicAdd(&g_counter, r);   // block base
    }
    __syncthreads();
    int base = ws[8] + ws[w] + incl - degp;
    if (i < N_NODES) {
        g_rowptr[i] = base;
        g_rowcur[i] = base;
        g_rowend[i] = base + degp;
        float dd = rsqrtf((float)(d + 1));
        g_dis[i] = dd;
        for (int q = d; q < degp; q++) g_colidx[base + q] = N_NODES;
#pragma unroll
        for (int q = 0; q < 4; q++) {
            float4 v = xv[q];
            v.x *= dd; v.y *= dd; v.z *= dd; v.w *= dd;
            f[i * 4 + q] = v;
        }
    }
}

// scatter 4 edges per thread (edge loads pre-wait -> overlap with k_base)
__global__ void k_scatter(const void* __restrict__ ei) {
    PDL_TRIGGER();
    __shared__ int s_is64;
    if (threadIdx.x == 0) s_is64 = probe_is64(ei);
    __syncthreads();
    int t = blockIdx.x * blockDim.x + threadIdx.x;

    int s[4], d[4];
    bool haveEdges = (t < N_EDGES / 4);
    if (haveEdges) {
        if (s_is64) {
            const longlong2* ps = (const longlong2*)ei + t * 2;
            const longlong2* pd = (const longlong2*)ei + N_EDGES / 2 + t * 2;
            longlong2 a = __ldg(&ps[0]), b = __ldg(&ps[1]);
            longlong2 c = __ldg(&pd[0]), e = __ldg(&pd[1]);
            s[0] = (int)a.x; s[1] = (int)a.y; s[2] = (int)b.x; s[3] = (int)b.y;
            d[0] = (int)c.x; d[1] = (int)c.y; d[2] = (int)e.x; d[3] = (int)e.y;
        } else {
            int4 a = __ldg((const int4*)ei + t);
            int4 c = __ldg((const int4*)ei + N_EDGES / 4 + t);
            s[0] = a.x; s[1] = a.y; s[2] = a.z; s[3] = a.w;
            d[0] = c.x; d[1] = c.y; d[2] = c.z; d[3] = c.w;
        }
    }

    PDL_WAIT();                       // needs g_rowcur

    if (haveEdges) {
#pragma unroll
        for (int q = 0; q < 4; q++) {
            if (d[q] >= 0 && d[q] < N_NODES) {
                int src = (s[q] >= 0 && s[q] < N_NODES) ? s[q] : N_NODES;
                int p = atomicAdd(&g_rowcur[d[q]], 1);
                g_colidx[p] = src;
            }
        }
    }
}

// ---------------- aggregation kernels (R11 unroll-8, ordering-stable) --------
__global__ void k_agg16(const float* __restrict__ g, float* __restrict__ agg) {
    PDL_TRIGGER();
    int t = blockIdx.x * blockDim.x + threadIdx.x;
    int node = t >> 4;
    int lane = t & 15;
    PDL_WAIT();
    if (node >= N_NODES) return;

    float acc = __ldg(&g[node * 16 + lane]);
    int p   = g_rowptr[node];
    int end = g_rowend[node];
    while (p + 8 <= end) {
        int4 a = __ldg((const int4*)&g_colidx[p]);
        int4 b = __ldg((const int4*)&g_colidx[p + 4]);
        acc += __ldg(&g[a.x * 16 + lane]);
        acc += __ldg(&g[a.y * 16 + lane]);
        acc += __ldg(&g[a.z * 16 + lane]);
        acc += __ldg(&g[a.w * 16 + lane]);
        acc += __ldg(&g[b.x * 16 + lane]);
        acc += __ldg(&g[b.y * 16 + lane]);
        acc += __ldg(&g[b.z * 16 + lane]);
        acc += __ldg(&g[b.w * 16 + lane]);
        p += 8;
    }
    if (p < end) {
        int4 a = __ldg((const int4*)&g_colidx[p]);
        acc += __ldg(&g[a.x * 16 + lane]);
        acc += __ldg(&g[a.y * 16 + lane]);
        acc += __ldg(&g[a.z * 16 + lane]);
        acc += __ldg(&g[a.w * 16 + lane]);
    }
    agg[node * 16 + lane] = acc * g_dis[node];
}

__global__ void k_agg32(const float* __restrict__ g, float* __restrict__ agg) {
    PDL_TRIGGER();
    int warp = (blockIdx.x * blockDim.x + threadIdx.x) >> 5;
    int lane = threadIdx.x & 31;
    PDL_WAIT();
    if (warp >= N_NODES) return;

    float acc = __ldg(&g[warp * 32 + lane]);
    int p   = g_rowptr[warp];
    int end = g_rowend[warp];
    while (p + 8 <= end) {
        int4 a = __ldg((const int4*)&g_colidx[p]);
        int4 b = __ldg((const int4*)&g_colidx[p + 4]);
        acc += __ldg(&g[(size_t)a.x * 32 + lane]);
        acc += __ldg(&g[(size_t)a.y * 32 + lane]);
        acc += __ldg(&g[(size_t)a.z * 32 + lane]);
        acc += __ldg(&g[(size_t)a.w * 32 + lane]);
        acc += __ldg(&g[(size_t)b.x * 32 + lane]);
        acc += __ldg(&g[(size_t)b.y * 32 + lane]);
        acc += __ldg(&g[(size_t)b.z * 32 + lane]);
        acc += __ldg(&g[(size_t)b.w * 32 + lane]);
        p += 8;
    }
    if (p < end) {
        int4 a = __ldg((const int4*)&g_colidx[p]);
        acc += __ldg(&g[(size_t)a.x * 32 + lane]);
        acc += __ldg(&g[(size_t)a.y * 32 + lane]);
        acc += __ldg(&g[(size_t)a.z * 32 + lane]);
        acc += __ldg(&g[(size_t)a.w * 32 + lane]);
    }
    agg[warp * 32 + lane] = acc * g_dis[warp];
}

__global__ void k_agg64(const float* __restrict__ g, float* __restrict__ agg) {
    PDL_TRIGGER();
    int warp = (blockIdx.x * blockDim.x + threadIdx.x) >> 5;
    int lane = threadIdx.x & 31;
    PDL_WAIT();
    if (warp >= N_NODES) return;

    const float2* g2 = (const float2*)g;
    float2 acc = __ldg(&g2[(size_t)warp * 32 + lane]);
    int p   = g_rowptr[warp];
    int end = g_rowend[warp];
    while (p + 8 <= end) {
        int4 ia = __ldg((const int4*)&g_colidx[p]);
        int4 ib = __ldg((const int4*)&g_colidx[p + 4]);
        float2 v0 = __ldg(&g2[(size_t)ia.x * 32 + lane]);
        float2 v1 = __ldg(&g2[(size_t)ia.y * 32 + lane]);
        float2 v2 = __ldg(&g2[(size_t)ia.z * 32 + lane]);
        float2 v3 = __ldg(&g2[(size_t)ia.w * 32 + lane]);
        float2 v4 = __ldg(&g2[(size_t)ib.x * 32 + lane]);
        float2 v5 = __ldg(&g2[(size_t)ib.y * 32 + lane]);
        float2 v6 = __ldg(&g2[(size_t)ib.z * 32 + lane]);
        float2 v7 = __ldg(&g2[(size_t)ib.w * 32 + lane]);
        acc.x += v0.x + v1.x + v2.x + v3.x + v4.x + v5.x + v6.x + v7.x;
        acc.y += v0.y + v1.y + v2.y + v3.y + v4.y + v5.y + v6.y + v7.y;
        p += 8;
    }
    if (p < end) {
        int4 ia = __ldg((const int4*)&g_colidx[p]);
        float2 v0 = __ldg(&g2[(size_t)ia.x * 32 + lane]);
        float2 v1 = __ldg(&g2[(size_t)ia.y * 32 + lane]);
        float2 v2 = __ldg(&g2[(size_t)ia.z * 32 + lane]);
        float2 v3 = __ldg(&g2[(size_t)ia.w * 32 + lane]);
        acc.x += v0.x + v1.x + v2.x + v3.x;
        acc.y += v0.y + v1.y + v2.y + v3.y;
    }
    float dd = g_dis[warp];
    float2 o; o.x = acc.x * dd; o.y = acc.y * dd;
    ((float2*)agg)[(size_t)warp * 32 + lane] = o;
}

// ---------------- register-tiled GEMM + bias + relu (+dis) ------------------
// weights/bias staged BEFORE PDL wait (pure inputs) -> overlap predecessor tail
template <int DIN, int DOUT, bool SCALE>
__global__ void __launch_bounds__(256) k_gemm2(
        const float* __restrict__ in,
        const float* __restrict__ W,
        const float* __restrict__ b,
        float* __restrict__ out) {
    PDL_TRIGGER();
    constexpr int NB  = 64;
    constexpr int TN  = (DOUT >= 32) ? 8 : 4;
    constexpr int TX  = DOUT / TN;
    constexpr int TY  = 256 / TX;
    constexpr int TM  = NB / TY;
    constexpr int KC  = (DIN * DOUT >= 8192) ? 32 : DIN;
    constexpr int NKC = DIN / KC;
    constexpr int INP = KC + 4;                    // float4-aligned padded rows
    constexpr int SWW = DOUT + 2 * (DOUT / 32) + 2;

    __shared__ __align__(16) float inS[NB * INP];
    __shared__ __align__(16) float Ws[KC * SWW];

    const int tid  = threadIdx.x;
    const int tx   = tid % TX;
    const int ty   = tid / TX;
    const int node0 = blockIdx.x * NB;

    // ---- pre-wait prologue: bias + weight chunk 0 (inputs only) ----
    float bb[TN];
#pragma unroll
    for (int j = 0; j < TN; j++) bb[j] = __ldg(&b[tx * TN + j]);
    for (int i = tid; i < KC * DOUT / 2; i += 256) {
        int r = i / (DOUT / 2), c = 2 * (i - r * (DOUT / 2));
        float2 wv = __ldg((const float2*)&W[(size_t)r * DOUT + c]);
        *(float2*)&Ws[r * SWW + c + 2 * (c >> 5)] = wv;
    }

    PDL_WAIT();                        // needs `in`

    // ---- input chunk 0 (float4) ----
    for (int i = tid; i < NB * KC / 4; i += 256) {
        int r = i / (KC / 4), c4 = 4 * (i - r * (KC / 4));
        int node = node0 + r;
        float4 v = make_float4(0.f, 0.f, 0.f, 0.f);
        if (node < N_NODES) v = __ldg((const float4*)&in[(size_t)node * DIN + c4]);
        *(float4*)&inS[r * INP + c4] = v;
    }
    __syncthreads();

    unsigned long long acc[TM][TN / 2];
#pragma unroll
    for (int m = 0; m < TM; m++)
#pragma unroll
        for (int j = 0; j < TN / 2; j++) acc[m][j] = 0ull;

    for (int kc = 0; kc < NKC; kc++) {
#pragma unroll
        for (int k = 0; k < KC; k++) {
            unsigned long long a2[TM];
#pragma unroll
            for (int m = 0; m < TM; m++) {
                float a = inS[(ty * TM + m) * INP + k];
                a2[m] = pack2(a, a);
            }
#pragma unroll
            for (int j = 0; j < TN / 2; j++) {
                int c = tx * TN + 2 * j;
                float2 wv = *reinterpret_cast<const float2*>(
                    &Ws[k * SWW + c + 2 * (c >> 5)]);
                unsigned long long w2 = pack2(wv.x, wv.y);
#pragma unroll
                for (int m = 0; m < TM; m++)
                    acc[m][j] = fma2(a2[m], w2, acc[m][j]);
            }
        }
        if (kc + 1 < NKC) {
            const int k0 = (kc + 1) * KC;
            __syncthreads();
            for (int i = tid; i < KC * DOUT / 2; i += 256) {
                int r = i / (DOUT / 2), c = 2 * (i - r * (DOUT / 2));
                float2 wv = __ldg((const float2*)&W[(size_t)(k0 + r) * DOUT + c]);
                *(float2*)&Ws[r * SWW + c + 2 * (c >> 5)] = wv;
            }
            for (int i = tid; i < NB * KC / 4; i += 256) {
                int r = i / (KC / 4), c4 = 4 * (i - r * (KC / 4));
                int node = node0 + r;
                float4 v = make_float4(0.f, 0.f, 0.f, 0.f);
                if (node < N_NODES)
                    v = __ldg((const float4*)&in[(size_t)node * DIN + k0 + c4]);
                *(float4*)&inS[r * INP + c4] = v;
            }
            __syncthreads();
        }
    }

#pragma unroll
    for (int m = 0; m < TM; m++) {
        int node = node0 + ty * TM + m;
        if (node >= N_NODES) continue;
        float sc = SCALE ? g_dis[node] : 1.f;
        float vals[TN];
#pragma unroll
        for (int j = 0; j < TN / 2; j++) {
            float v0, v1;
            unpack2(acc[m][j], v0, v1);
            v0 += bb[2 * j];     v1 += bb[2 * j + 1];
            v0 = v0 > 0.f ? v0 : 0.f;
            v1 = v1 > 0.f ? v1 : 0.f;
            vals[2 * j]     = v0 * sc;
            vals[2 * j + 1] = v1 * sc;
        }
        float4* o = (float4*)(out + (size_t)node * DOUT + tx * TN);
#pragma unroll
        for (int q = 0; q < TN / 4; q++)
            o[q] = make_float4(vals[4 * q], vals[4 * q + 1],
                               vals[4 * q + 2], vals[4 * q + 3]);
    }
}

// ---------------- fused dense l2+l3 + state reset ----------------------------
__global__ void __launch_bounds__(256) k_l23(
        const float* __restrict__ in,
        const float* __restrict__ W2, const float* __restrict__ b2,
        const float* __restrict__ W3, const float* __restrict__ b3,
        float* __restrict__ out) {
    PDL_TRIGGER();
    __shared__ __align__(16) float h1S[64 * 68];
    __shared__ float h2S[64 * 34];
    __shared__ float W2s[64 * 34];
    __shared__ float W3s[32 * 18];
    __shared__ float b2s[32];
    __shared__ float b3s[16];

    const int tid   = threadIdx.x;
    const int node0 = blockIdx.x * 64;

    // ---- pre-wait prologue: dense weights + biases (inputs only) ----
    for (int i = tid; i < 64 * 32; i += 256) {
        int r = i >> 5, c = i & 31;
        W2s[r * 34 + c] = __ldg(&W2[i]);
    }
    for (int i = tid; i < 32 * 16; i += 256) {
        int r = i >> 4, c = i & 15;
        W3s[r * 18 + c] = __ldg(&W3[i]);
    }
    if (tid < 32) b2s[tid] = __ldg(&b2[tid]);
    else if (tid < 48) b3s[tid - 32] = __ldg(&b3[tid - 32]);

    PDL_WAIT();                        // needs `in` (and all upstream complete)

    // restore the zero-state invariant for the next run (safe: upstream done)
    {
        int t = blockIdx.x * blockDim.x + tid;
        int stride = gridDim.x * blockDim.x;
        for (int i = t; i < N_NODES; i += stride) g_deg[i] = 0;
        if (t == 0) g_counter = 0;
    }

    for (int i = tid; i < 64 * 16; i += 256) {
        int r = i >> 4, c4 = (i & 15) * 4;
        int n = node0 + r;
        float4 v = make_float4(0.f, 0.f, 0.f, 0.f);
        if (n < N_NODES) v = __ldg((const float4*)&in[(size_t)n * 64 + c4]);
        *(float4*)&h1S[r * 68 + c4] = v;
    }
    __syncthreads();

    {
        int r  = tid >> 2;
        int c0 = (tid & 3) * 8;
        unsigned long long acc[4] = {0ull, 0ull, 0ull, 0ull};
#pragma unroll
        for (int k = 0; k < 64; k++) {
            float a = h1S[r * 68 + k];
            unsigned long long a2 = pack2(a, a);
#pragma unroll
            for (int j = 0; j < 4; j++) {
                float2 wv = *reinterpret_cast<const float2*>(&W2s[k * 34 + c0 + 2 * j]);
                acc[j] = fma2(a2, pack2(wv.x, wv.y), acc[j]);
            }
        }
#pragma unroll
        for (int j = 0; j < 4; j++) {
            float v0, v1;
            unpack2(acc[j], v0, v1);
            v0 += b2s[c0 + 2 * j];     v1 += b2s[c0 + 2 * j + 1];
            h2S[r * 34 + c0 + 2 * j]     = v0 > 0.f ? v0 : 0.f;
            h2S[r * 34 + c0 + 2 * j + 1] = v1 > 0.f ? v1 : 0.f;
        }
    }
    __syncthreads();

    {
        int r  = tid >> 2;
        int c0 = (tid & 3) * 4;
        unsigned long long acc[2] = {0ull, 0ull};
#pragma unroll
        for (int k = 0; k < 32; k++) {
            float a = h2S[r * 34 + k];
            unsigned long long a2 = pack2(a, a);
#pragma unroll
            for (int j = 0; j < 2; j++) {
                float2 wv = *reinterpret_cast<const float2*>(&W3s[k * 18 + c0 + 2 * j]);
                acc[j] = fma2(a2, pack2(wv.x, wv.y), acc[j]);
            }
        }
        int n = node0 + r;
        if (n < N_NODES) {
            float v[4];
            unpack2(acc[0], v[0], v[1]);
            unpack2(acc[1], v[2], v[3]);
#pragma unroll
            for (int j = 0; j < 4; j++) {
                v[j] += b3s[c0 + j];
                v[j] = v[j] > 0.f ? v[j] : 0.f;
            }
            *(float4*)(out + (size_t)n * 16 + c0) = make_float4(v[0], v[1], v[2], v[3]);
        }
    }
}

// ---------------- PDL launch helper -------------------------------------------
#define PDL_LAUNCH(kernel, grid, block, ...) do {                          \
    cudaLaunchAttribute _a[1];                                             \
    memset(&_a[0], 0, sizeof(_a[0]));                                      \
    _a[0].id = cudaLaunchAttributeProgrammaticStreamSerialization;         \
    *(int*)&_a[0].val = 1;  /* allowedCount = 1 */                         \
    cudaLaunchConfig_t _c = {};                                            \
    _c.gridDim = dim3(grid); _c.blockDim = dim3(block);                    \
    _c.dynamicSmemBytes = 0; _c.stream = 0;                                \
    _c.attrs = _a; _c.numAttrs = 1;                                        \
    cudaLaunchKernelEx(&_c, kernel, ##__VA_ARGS__);                        \
} while (0)

// ---------------- launch ------------------------------------------------------
extern "C" void kernel_launch(void* const* d_in, const int* in_sizes, int n_in,
                              void* d_out, int out_size) {
    const float* x  = (const float*)d_in[0];
    const void*  ei = d_in[1];
    const float *W1 = (const float*)d_in[2],  *b1 = (const float*)d_in[3];
    const float *W2 = (const float*)d_in[4],  *b2 = (const float*)d_in[5];
    const float *W3 = (const float*)d_in[6],  *b3 = (const float*)d_in[7];
    const float *Wl1= (const float*)d_in[8],  *bl1= (const float*)d_in[9];
    const float *Wl2= (const float*)d_in[10], *bl2= (const float*)d_in[11];
    const float *Wl3= (const float*)d_in[12], *bl3= (const float*)d_in[13];
    float* out = (float*)d_out;

    float *f16, *a16, *f32, *a32, *f64, *a64, *h128, *h64;
    cudaGetSymbolAddress((void**)&f16, g_f16);
    cudaGetSymbolAddress((void**)&a16, g_a16);
    cudaGetSymbolAddress((void**)&f32, g_f32);
    cudaGetSymbolAddress((void**)&a32, g_a32);
    cudaGetSymbolAddress((void**)&f64, g_f64);
    cudaGetSymbolAddress((void**)&a64, g_a64);
    cudaGetSymbolAddress((void**)&h128, g_h128);
    cudaGetSymbolAddress((void**)&h64, g_h64);

    const int TB = 256;
    const int nodeBlocks  = (N_NODES + TB - 1) / TB;
    const int edge8Blocks = (N_EDGES / 8 + TB - 1) / TB;
    const int edge4Blocks = (N_EDGES / 4 + TB - 1) / TB;
    const int tileBlocks  = (N_NODES + 63) / 64;
    const int hwBlocks    = (N_NODES * 16 + TB - 1) / TB;
    const int wBlocks     = (N_NODES * 32 + TB - 1) / TB;

    // --- CSR build (+ x scaling inside k_base) ---
    k_hist<<<edge8Blocks, TB>>>(ei);
    PDL_LAUNCH(k_base, nodeBlocks, TB, (const float4*)x, (float4*)f16);
    PDL_LAUNCH(k_scatter, edge4Blocks, TB, ei);

    // --- conv 1: 16 -> 32 ---
    PDL_LAUNCH(k_agg16, hwBlocks, TB, (const float*)f16, a16);
    PDL_LAUNCH((k_gemm2<16, 32, true>), tileBlocks, TB,
               (const float*)a16, W1, b1, f32);

    // --- conv 2: 32 -> 64 ---
    PDL_LAUNCH(k_agg32, wBlocks, TB, (const float*)f32, a32);
    PDL_LAUNCH((k_gemm2<32, 64, true>), tileBlocks, TB,
               (const float*)a32, W2, b2, f64);

    // --- conv 3: 64 -> 128 ---
    PDL_LAUNCH(k_agg64, wBlocks, TB, (const float*)f64, a64);
    PDL_LAUNCH((k_gemm2<64, 128, false>), tileBlocks, TB,
               (const float*)a64, W3, b3, h128);

    // --- dense layers ---
    PDL_LAUNCH((k_gemm2<128, 64, false>), tileBlocks, TB,
               (const float*)h128, Wl1, bl1, h64);
    PDL_LAUNCH(k_l23, tileBlocks, TB,
               (const float*)h64, Wl2, bl2, Wl3, bl3, out);
}

// round 16
// speedup vs baseline: 1.0322x; 1.0193x over previous
#include <cuda_runtime.h>
#include <cuda_bf16.h>
#include <cuda_fp16.h>
#include <stdint.h>
#include <string.h>

#define N_NODES 50000
#define N_EDGES 800000
#define COLCAP (N_EDGES + 4 * N_NODES + 64)   // padded colidx capacity

// ---------------- PDL primitives (sm_90+) ------------------------------------
#define PDL_TRIGGER() asm volatile("griddepcontrol.launch_dependents;" ::: "memory")
#define PDL_WAIT()    asm volatile("griddepcontrol.wait;" ::: "memory")

// ---------------- scratch (device globals; zero-initialized at load) --------
// invariant: g_deg all-zero and g_counter==0 at entry of every run
// (restored by the tail of k_l23 each run)
__device__ int   g_counter;
__device__ int   g_deg[N_NODES];
__device__ int   g_rowptr[N_NODES];      // bucket start (multiple of 4)
__device__ int   g_rowend[N_NODES];      // bucket padded end (multiple of 4)
__device__ int   g_rowcur[N_NODES];      // scatter cursor
__device__ int   g_colidx[COLCAP];
__device__ float g_dis[N_NODES];
// gather sources have one extra always-zero row (index N_NODES)
__device__ float  g_f16[(N_NODES + 1) * 16];          // dis*x (fp32: mean-zero data)
__device__ float  g_a16[N_NODES * 16];                // agg16 out
__device__ __align__(16) __half g_c1h[(N_NODES + 1) * 32];  // conv1 out (fp16, post-relu)
__device__ float  g_a32[N_NODES * 32];                // agg32 out
__device__ __align__(16) __half g_c2h[(N_NODES + 1) * 64];  // conv2 out (fp16, post-relu)
__device__ float  g_a64[N_NODES * 64];                // agg64 out
__device__ float  g_h128[N_NODES * 128];              // conv3 out
__device__ float  g_h64[N_NODES * 64];                // dense l1 out

// ---------------- packed f32x2 helpers (Blackwell) ---------------------------
__device__ __forceinline__ unsigned long long pack2(float x, float y) {
    unsigned long long r;
    asm("mov.b64 %0, {%1, %2};" : "=l"(r) : "f"(x), "f"(y));
    return r;
}
__device__ __forceinline__ void unpack2(unsigned long long v, float& x, float& y) {
    asm("mov.b64 {%0, %1}, %2;" : "=f"(x), "=f"(y) : "l"(v));
}
__device__ __forceinline__ unsigned long long fma2(unsigned long long a,
                                                   unsigned long long b,
                                                   unsigned long long c) {
    unsigned long long d;
    asm("fma.rn.f32x2 %0, %1, %2, %3;" : "=l"(d) : "l"(a), "l"(b), "l"(c));
    return d;
}

// per-block edge-dtype probe (reads only kernel inputs)
__device__ __forceinline__ int probe_is64(const void* ei) {
    const long long* p = (const long long*)ei;
    int ok64 = 1;
#pragma unroll 8
    for (int q = 0; q < 64; q++) {
        long long v = p[q];
        if (v < 0 || v >= N_NODES) { ok64 = 0; break; }
    }
    return ok64;
}

// ---------------- CSR build ---------------------------------------------------
// 8 dst indices per thread — integer histogram atomics are exactly commutative.
__global__ void k_hist(const void* __restrict__ ei) {
    PDL_TRIGGER();
    __shared__ int s_is64;
    if (threadIdx.x == 0) s_is64 = probe_is64(ei);
    __syncthreads();
    int t = blockIdx.x * blockDim.x + threadIdx.x;
    if (t >= N_EDGES / 8) return;
    int d[8];
    if (s_is64) {
        const longlong2* p = (const longlong2*)ei + N_EDGES / 2 + (long long)t * 4;
        longlong2 a = __ldg(&p[0]), b = __ldg(&p[1]);
        longlong2 c = __ldg(&p[2]), e = __ldg(&p[3]);
        d[0] = (int)a.x; d[1] = (int)a.y; d[2] = (int)b.x; d[3] = (int)b.y;
        d[4] = (int)c.x; d[5] = (int)c.y; d[6] = (int)e.x; d[7] = (int)e.y;
    } else {
        const int4* p = (const int4*)ei + N_EDGES / 4 + (long long)t * 2;
        int4 a = __ldg(&p[0]), b = __ldg(&p[1]);
        d[0] = a.x; d[1] = a.y; d[2] = a.z; d[3] = a.w;
        d[4] = b.x; d[5] = b.y; d[6] = b.z; d[7] = b.w;
    }
#pragma unroll
    for (int q = 0; q < 8; q++)
        if (d[q] >= 0 && d[q] < N_NODES) atomicAdd(&g_deg[d[q]], 1);
}

// bucket bases (padded to multiples of 4): block scan + one atomic per block
__global__ void k_base() {
    PDL_TRIGGER();
    PDL_WAIT();                       // needs g_deg complete
    __shared__ int ws[9];
    int i = blockIdx.x * blockDim.x + threadIdx.x;
    int d    = (i < N_NODES) ? g_deg[i] : 0;
    int degp = (d + 3) & ~3;
    int lane = threadIdx.x & 31, w = threadIdx.x >> 5;
    int incl = degp;
#pragma unroll
    for (int off = 1; off < 32; off <<= 1) {
        int t = __shfl_up_sync(0xffffffffu, incl, off);
        if (lane >= off) incl += t;
    }
    if (lane == 31) ws[w] = incl;
    __syncthreads();
    if (threadIdx.x == 0) {
        int r = 0;
#pragma unroll
        for (int j = 0; j < 8; j++) { int t = ws[j]; ws[j] = r; r += t; }
        ws[8] = atomicAdd(&g_counter, r);   // block base
    }
    __syncthreads();
    int base = ws[8] + ws[w] + incl - degp;
    if (i < N_NODES) {
        g_rowptr[i] = base;
        g_rowcur[i] = base;
        g_rowend[i] = base + degp;
        g_dis[i]    = rsqrtf((float)(d + 1));
        for (int q = d; q < degp; q++) g_colidx[base + q] = N_NODES;
    }
}

// scatter 4 edges per thread + scale one float4 of layer-1 input.
// Edge + x loads (pure inputs) run BEFORE the PDL wait -> overlap with k_base.
__global__ void k_scatter(const void* __restrict__ ei,
                          const float4* __restrict__ x, float4* __restrict__ f) {
    PDL_TRIGGER();
    __shared__ int s_is64;
    if (threadIdx.x == 0) s_is64 = probe_is64(ei);
    __syncthreads();
    int t = blockIdx.x * blockDim.x + threadIdx.x;

    int s[4], d[4];
    bool haveEdges = (t < N_EDGES / 4);
    if (haveEdges) {
        if (s_is64) {
            const longlong2* ps = (const longlong2*)ei + t * 2;
            const longlong2* pd = (const longlong2*)ei + N_EDGES / 2 + t * 2;
            longlong2 a = __ldg(&ps[0]), b = __ldg(&ps[1]);
            longlong2 c = __ldg(&pd[0]), e = __ldg(&pd[1]);
            s[0] = (int)a.x; s[1] = (int)a.y; s[2] = (int)b.x; s[3] = (int)b.y;
            d[0] = (int)c.x; d[1] = (int)c.y; d[2] = (int)e.x; d[3] = (int)e.y;
        } else {
            int4 a = __ldg((const int4*)ei + t);
            int4 c = __ldg((const int4*)ei + N_EDGES / 4 + t);
            s[0] = a.x; s[1] = a.y; s[2] = a.z; s[3] = a.w;
            d[0] = c.x; d[1] = c.y; d[2] = c.z; d[3] = c.w;
        }
    }
    float4 xv = make_float4(0.f, 0.f, 0.f, 0.f);
    bool haveX = (t < N_NODES * 4);
    if (haveX) xv = __ldg(&x[t]);

    PDL_WAIT();                       // needs g_rowcur / g_dis

    if (haveEdges) {
#pragma unroll
        for (int q = 0; q < 4; q++) {
            if (d[q] >= 0 && d[q] < N_NODES) {
                int src = (s[q] >= 0 && s[q] < N_NODES) ? s[q] : N_NODES;
                int p = atomicAdd(&g_rowcur[d[q]], 1);
                g_colidx[p] = src;
            }
        }
    }
    if (haveX) {
        float dd = g_dis[t >> 2];
        xv.x *= dd; xv.y *= dd; xv.z *= dd; xv.w *= dd;
        f[t] = xv;
    }
}

// ---------------- agg16: fp32 source (layer-1 input, mean-zero) --------------
__global__ void k_agg16(const float* __restrict__ g, float* __restrict__ agg) {
    PDL_TRIGGER();
    int t = blockIdx.x * blockDim.x + threadIdx.x;
    int node = t >> 4;
    int lane = t & 15;
    PDL_WAIT();
    if (node >= N_NODES) return;

    float acc = __ldg(&g[node * 16 + lane]);
    int p   = g_rowptr[node];
    int end = g_rowend[node];
    while (p + 8 <= end) {
        int4 a = __ldg((const int4*)&g_colidx[p]);
        int4 b = __ldg((const int4*)&g_colidx[p + 4]);
        acc += __ldg(&g[a.x * 16 + lane]);
        acc += __ldg(&g[a.y * 16 + lane]);
        acc += __ldg(&g[a.z * 16 + lane]);
        acc += __ldg(&g[a.w * 16 + lane]);
        acc += __ldg(&g[b.x * 16 + lane]);
        acc += __ldg(&g[b.y * 16 + lane]);
        acc += __ldg(&g[b.z * 16 + lane]);
        acc += __ldg(&g[b.w * 16 + lane]);
        p += 8;
    }
    if (p < end) {
        int4 a = __ldg((const int4*)&g_colidx[p]);
        acc += __ldg(&g[a.x * 16 + lane]);
        acc += __ldg(&g[a.y * 16 + lane]);
        acc += __ldg(&g[a.z * 16 + lane]);
        acc += __ldg(&g[a.w * 16 + lane]);
    }
    agg[node * 16 + lane] = acc * g_dis[node];
}

// ---------------- agg32: fp16 source, fp32 accumulation (R11 order) ----------
__global__ void k_agg32h(const __half* __restrict__ g, float* __restrict__ agg) {
    PDL_TRIGGER();
    int warp = (blockIdx.x * blockDim.x + threadIdx.x) >> 5;
    int lane = threadIdx.x & 31;
    PDL_WAIT();
    if (warp >= N_NODES) return;

    float acc = __half2float(__ldg(&g[(size_t)warp * 32 + lane]));
    int p   = g_rowptr[warp];
    int end = g_rowend[warp];
    while (p + 8 <= end) {
        int4 a = __ldg((const int4*)&g_colidx[p]);
        int4 b = __ldg((const int4*)&g_colidx[p + 4]);
        __half h0 = __ldg(&g[(size_t)a.x * 32 + lane]);
        __half h1 = __ldg(&g[(size_t)a.y * 32 + lane]);
        __half h2 = __ldg(&g[(size_t)a.z * 32 + lane]);
        __half h3 = __ldg(&g[(size_t)a.w * 32 + lane]);
        __half h4 = __ldg(&g[(size_t)b.x * 32 + lane]);
        __half h5 = __ldg(&g[(size_t)b.y * 32 + lane]);
        __half h6 = __ldg(&g[(size_t)b.z * 32 + lane]);
        __half h7 = __ldg(&g[(size_t)b.w * 32 + lane]);
        acc += __half2float(h0);
        acc += __half2float(h1);
        acc += __half2float(h2);
        acc += __half2float(h3);
        acc += __half2float(h4);
        acc += __half2float(h5);
        acc += __half2float(h6);
        acc += __half2float(h7);
        p += 8;
    }
    if (p < end) {
        int4 a = __ldg((const int4*)&g_colidx[p]);
        acc += __half2float(__ldg(&g[(size_t)a.x * 32 + lane]));
        acc += __half2float(__ldg(&g[(size_t)a.y * 32 + lane]));
        acc += __half2float(__ldg(&g[(size_t)a.z * 32 + lane]));
        acc += __half2float(__ldg(&g[(size_t)a.w * 32 + lane]));
    }
    agg[(size_t)warp * 32 + lane] = acc * g_dis[warp];
}

// ---------------- agg64: fp16 source (half2/lane), fp32 accumulation ---------
__global__ void k_agg64h(const __half2* __restrict__ g2, float* __restrict__ agg) {
    PDL_TRIGGER();
    int warp = (blockIdx.x * blockDim.x + threadIdx.x) >> 5;
    int lane = threadIdx.x & 31;
    PDL_WAIT();
    if (warp >= N_NODES) return;

    float2 acc = __half22float2(__ldg(&g2[(size_t)warp * 32 + lane]));
    int p   = g_rowptr[warp];
    int end = g_rowend[warp];
    while (p + 8 <= end) {
        int4 ia = __ldg((const int4*)&g_colidx[p]);
        int4 ib = __ldg((const int4*)&g_colidx[p + 4]);
        float2 v0 = __half22float2(__ldg(&g2[(size_t)ia.x * 32 + lane]));
        float2 v1 = __half22float2(__ldg(&g2[(size_t)ia.y * 32 + lane]));
        float2 v2 = __half22float2(__ldg(&g2[(size_t)ia.z * 32 + lane]));
        float2 v3 = __half22float2(__ldg(&g2[(size_t)ia.w * 32 + lane]));
        float2 v4 = __half22float2(__ldg(&g2[(size_t)ib.x * 32 + lane]));
        float2 v5 = __half22float2(__ldg(&g2[(size_t)ib.y * 32 + lane]));
        float2 v6 = __half22float2(__ldg(&g2[(size_t)ib.z * 32 + lane]));
        float2 v7 = __half22float2(__ldg(&g2[(size_t)ib.w * 32 + lane]));
        acc.x += v0.x + v1.x + v2.x + v3.x + v4.x + v5.x + v6.x + v7.x;
        acc.y += v0.y + v1.y + v2.y + v3.y + v4.y + v5.y + v6.y + v7.y;
        p += 8;
    }
    if (p < end) {
        int4 ia = __ldg((const int4*)&g_colidx[p]);
        float2 v0 = __half22float2(__ldg(&g2[(size_t)ia.x * 32 + lane]));
        float2 v1 = __half22float2(__ldg(&g2[(size_t)ia.y * 32 + lane]));
        float2 v2 = __half22float2(__ldg(&g2[(size_t)ia.z * 32 + lane]));
        float2 v3 = __half22float2(__ldg(&g2[(size_t)ia.w * 32 + lane]));
        acc.x += v0.x + v1.x + v2.x + v3.x;
        acc.y += v0.y + v1.y + v2.y + v3.y;
    }
    float dd = g_dis[warp];
    float2 o; o.x = acc.x * dd; o.y = acc.y * dd;
    ((float2*)agg)[(size_t)warp * 32 + lane] = o;
}

// ---------------- register-tiled GEMM + bias + relu (+dis); fp32/fp16 out ----
template <int DIN, int DOUT, bool SCALE, bool HOUT>
__global__ void __launch_bounds__(256) k_gemm2(
        const float* __restrict__ in,
        const float* __restrict__ W,
        const float* __restrict__ b,
        void* __restrict__ out) {
    PDL_TRIGGER();
    constexpr int NB  = 64;
    constexpr int TN  = (DOUT >= 32) ? 8 : 4;
    constexpr int TX  = DOUT / TN;
    constexpr int TY  = 256 / TX;
    constexpr int TM  = NB / TY;
    constexpr int KC  = (DIN * DOUT >= 8192) ? 32 : DIN;
    constexpr int NKC = DIN / KC;
    constexpr int INP = KC + 4;
    constexpr int SWW = DOUT + 2 * (DOUT / 32) + 2;

    __shared__ __align__(16) float inS[NB * INP];
    __shared__ __align__(16) float Ws[KC * SWW];

    const int tid  = threadIdx.x;
    const int tx   = tid % TX;
    const int ty   = tid / TX;
    const int node0 = blockIdx.x * NB;

    float bb[TN];
#pragma unroll
    for (int j = 0; j < TN; j++) bb[j] = __ldg(&b[tx * TN + j]);
    for (int i = tid; i < KC * DOUT / 2; i += 256) {
        int r = i / (DOUT / 2), c = 2 * (i - r * (DOUT / 2));
        float2 wv = __ldg((const float2*)&W[(size_t)r * DOUT + c]);
        *(float2*)&Ws[r * SWW + c + 2 * (c >> 5)] = wv;
    }

    PDL_WAIT();

    for (int i = tid; i < NB * KC / 4; i += 256) {
        int r = i / (KC / 4), c4 = 4 * (i - r * (KC / 4));
        int node = node0 + r;
        float4 v = make_float4(0.f, 0.f, 0.f, 0.f);
        if (node < N_NODES) v = __ldg((const float4*)&in[(size_t)node * DIN + c4]);
        *(float4*)&inS[r * INP + c4] = v;
    }
    __syncthreads();

    unsigned long long acc[TM][TN / 2];
#pragma unroll
    for (int m = 0; m < TM; m++)
#pragma unroll
        for (int j = 0; j < TN / 2; j++) acc[m][j] = 0ull;

    for (int kc = 0; kc < NKC; kc++) {
#pragma unroll
        for (int k = 0; k < KC; k++) {
            unsigned long long a2[TM];
#pragma unroll
            for (int m = 0; m < TM; m++) {
                float a = inS[(ty * TM + m) * INP + k];
                a2[m] = pack2(a, a);
            }
#pragma unroll
            for (int j = 0; j < TN / 2; j++) {
                int c = tx * TN + 2 * j;
                float2 wv = *reinterpret_cast<const float2*>(
                    &Ws[k * SWW + c + 2 * (c >> 5)]);
                unsigned long long w2 = pack2(wv.x, wv.y);
#pragma unroll
                for (int m = 0; m < TM; m++)
                    acc[m][j] = fma2(a2[m], w2, acc[m][j]);
            }
        }
        if (kc + 1 < NKC) {
            const int k0 = (kc + 1) * KC;
            __syncthreads();
            for (int i = tid; i < KC * DOUT / 2; i += 256) {
                int r = i / (DOUT / 2), c = 2 * (i - r * (DOUT / 2));
                float2 wv = __ldg((const float2*)&W[(size_t)(k0 + r) * DOUT + c]);
                *(float2*)&Ws[r * SWW + c + 2 * (c >> 5)] = wv;
            }
            for (int i = tid; i < NB * KC / 4; i += 256) {
                int r = i / (KC / 4), c4 = 4 * (i - r * (KC / 4));
                int node = node0 + r;
                float4 v = make_float4(0.f, 0.f, 0.f, 0.f);
                if (node < N_NODES)
                    v = __ldg((const float4*)&in[(size_t)node * DIN + k0 + c4]);
                *(float4*)&inS[r * INP + c4] = v;
            }
            __syncthreads();
        }
    }

#pragma unroll
    for (int m = 0; m < TM; m++) {
        int node = node0 + ty * TM + m;
        if (node >= N_NODES) continue;
        float sc = SCALE ? g_dis[node] : 1.f;
        float vals[TN];
#pragma unroll
        for (int j = 0; j < TN / 2; j++) {
            float v0, v1;
            unpack2(acc[m][j], v0, v1);
            v0 += bb[2 * j];     v1 += bb[2 * j + 1];
            v0 = v0 > 0.f ? v0 : 0.f;
            v1 = v1 > 0.f ? v1 : 0.f;
            vals[2 * j]     = v0 * sc;
            vals[2 * j + 1] = v1 * sc;
        }
        if constexpr (HOUT) {
            // TN==8 for all HOUT instantiations -> one 16B store
            __align__(16) __half2 h[TN / 2];
#pragma unroll
            for (int j = 0; j < TN / 2; j++)
                h[j] = __floats2half2_rn(vals[2 * j], vals[2 * j + 1]);
            *(uint4*)((__half*)out + (size_t)node * DOUT + tx * TN) = *(uint4*)h;
        } else {
            float4* o = (float4*)((float*)out + (size_t)node * DOUT + tx * TN);
#pragma unroll
            for (int q = 0; q < TN / 4; q++)
                o[q] = make_float4(vals[4 * q], vals[4 * q + 1],
                                   vals[4 * q + 2], vals[4 * q + 3]);
        }
    }
}

// ---------------- fused dense l2+l3 + state reset ----------------------------
__global__ void __launch_bounds__(256) k_l23(
        const float* __restrict__ in,
        const float* __restrict__ W2, const float* __restrict__ b2,
        const float* __restrict__ W3, const float* __restrict__ b3,
        float* __restrict__ out) {
    PDL_TRIGGER();
    __shared__ __align__(16) float h1S[64 * 68];
    __shared__ float h2S[64 * 34];
    __shared__ float W2s[64 * 34];
    __shared__ float W3s[32 * 18];
    __shared__ float b2s[32];
    __shared__ float b3s[16];

    const int tid   = threadIdx.x;
    const int node0 = blockIdx.x * 64;

    for (int i = tid; i < 64 * 32; i += 256) {
        int r = i >> 5, c = i & 31;
        W2s[r * 34 + c] = __ldg(&W2[i]);
    }
    for (int i = tid; i < 32 * 16; i += 256) {
        int r = i >> 4, c = i & 15;
        W3s[r * 18 + c] = __ldg(&W3[i]);
    }
    if (tid < 32) b2s[tid] = __ldg(&b2[tid]);
    else if (tid < 48) b3s[tid - 32] = __ldg(&b3[tid - 32]);

    PDL_WAIT();

    {
        int t = blockIdx.x * blockDim.x + tid;
        int stride = gridDim.x * blockDim.x;
        for (int i = t; i < N_NODES; i += stride) g_deg[i] = 0;
        if (t == 0) g_counter = 0;
    }

    for (int i = tid; i < 64 * 16; i += 256) {
        int r = i >> 4, c4 = (i & 15) * 4;
        int n = node0 + r;
        float4 v = make_float4(0.f, 0.f, 0.f, 0.f);
        if (n < N_NODES) v = __ldg((const float4*)&in[(size_t)n * 64 + c4]);
        *(float4*)&h1S[r * 68 + c4] = v;
    }
    __syncthreads();

    {
        int r  = tid >> 2;
        int c0 = (tid & 3) * 8;
        unsigned long long acc[4] = {0ull, 0ull, 0ull, 0ull};
#pragma unroll
        for (int k = 0; k < 64; k++) {
            float a = h1S[r * 68 + k];
            unsigned long long a2 = pack2(a, a);
#pragma unroll
            for (int j = 0; j < 4; j++) {
                float2 wv = *reinterpret_cast<const float2*>(&W2s[k * 34 + c0 + 2 * j]);
                acc[j] = fma2(a2, pack2(wv.x, wv.y), acc[j]);
            }
        }
#pragma unroll
        for (int j = 0; j < 4; j++) {
            float v0, v1;
            unpack2(acc[j], v0, v1);
            v0 += b2s[c0 + 2 * j];     v1 += b2s[c0 + 2 * j + 1];
            h2S[r * 34 + c0 + 2 * j]     = v0 > 0.f ? v0 : 0.f;
            h2S[r * 34 + c0 + 2 * j + 1] = v1 > 0.f ? v1 : 0.f;
        }
    }
    __syncthreads();

    {
        int r  = tid >> 2;
        int c0 = (tid & 3) * 4;
        unsigned long long acc[2] = {0ull, 0ull};
#pragma unroll
        for (int k = 0; k < 32; k++) {
            float a = h2S[r * 34 + k];
            unsigned long long a2 = pack2(a, a);
#pragma unroll
            for (int j = 0; j < 2; j++) {
                float2 wv = *reinterpret_cast<const float2*>(&W3s[k * 18 + c0 + 2 * j]);
                acc[j] = fma2(a2, pack2(wv.x, wv.y), acc[j]);
            }
        }
        int n = node0 + r;
        if (n < N_NODES) {
            float v[4];
            unpack2(acc[0], v[0], v[1]);
            unpack2(acc[1], v[2], v[3]);
#pragma unroll
            for (int j = 0; j < 4; j++) {
                v[j] += b3s[c0 + j];
                v[j] = v[j] > 0.f ? v[j] : 0.f;
            }
            *(float4*)(out + (size_t)n * 16 + c0) = make_float4(v[0], v[1], v[2], v[3]);
        }
    }
}

// ---------------- PDL launch helper -------------------------------------------
#define PDL_LAUNCH(kernel, grid, block, ...) do {                          \
    cudaLaunchAttribute _a[1];                                             \
    memset(&_a[0], 0, sizeof(_a[0]));                                      \
    _a[0].id = cudaLaunchAttributeProgrammaticStreamSerialization;         \
    *(int*)&_a[0].val = 1;  /* allowedCount = 1 */                         \
    cudaLaunchConfig_t _c = {};                                            \
    _c.gridDim = dim3(grid); _c.blockDim = dim3(block);                    \
    _c.dynamicSmemBytes = 0; _c.stream = 0;                                \
    _c.attrs = _a; _c.numAttrs = 1;                                        \
    cudaLaunchKernelEx(&_c, kernel, ##__VA_ARGS__);                        \
} while (0)

// ---------------- launch ------------------------------------------------------
extern "C" void kernel_launch(void* const* d_in, const int* in_sizes, int n_in,
                              void* d_out, int out_size) {
    const float* x  = (const float*)d_in[0];
    const void*  ei = d_in[1];
    const float *W1 = (const float*)d_in[2],  *b1 = (const float*)d_in[3];
    const float *W2 = (const float*)d_in[4],  *b2 = (const float*)d_in[5];
    const float *W3 = (const float*)d_in[6],  *b3 = (const float*)d_in[7];
    const float *Wl1= (const float*)d_in[8],  *bl1= (const float*)d_in[9];
    const float *Wl2= (const float*)d_in[10], *bl2= (const float*)d_in[11];
    const float *Wl3= (const float*)d_in[12], *bl3= (const float*)d_in[13];
    float* out = (float*)d_out;

    float *f16, *a16, *a32, *a64, *h128, *h64;
    __half *c1h, *c2h;
    cudaGetSymbolAddress((void**)&f16, g_f16);
    cudaGetSymbolAddress((void**)&a16, g_a16);
    cudaGetSymbolAddress((void**)&c1h, g_c1h);
    cudaGetSymbolAddress((void**)&a32, g_a32);
    cudaGetSymbolAddress((void**)&c2h, g_c2h);
    cudaGetSymbolAddress((void**)&a64, g_a64);
    cudaGetSymbolAddress((void**)&h128, g_h128);
    cudaGetSymbolAddress((void**)&h64, g_h64);

    const int TB = 256;
    const int nodeBlocks  = (N_NODES + TB - 1) / TB;
    const int edge8Blocks = (N_EDGES / 8 + TB - 1) / TB;
    const int scat4Blocks = ((N_NODES * 4 > N_EDGES / 4 ? N_NODES * 4 : N_EDGES / 4)
                             + TB - 1) / TB;
    const int tileBlocks  = (N_NODES + 63) / 64;
    const int hwBlocks    = (N_NODES * 16 + TB - 1) / TB;
    const int wBlocks     = (N_NODES * 32 + TB - 1) / TB;

    // --- CSR build ---
    k_hist<<<edge8Blocks, TB>>>(ei);
    PDL_LAUNCH(k_base, nodeBlocks, TB);
    PDL_LAUNCH(k_scatter, scat4Blocks, TB, ei, (const float4*)x, (float4*)f16);

    // --- conv 1: 16 -> 32 (output fp16) ---
    PDL_LAUNCH(k_agg16, hwBlocks, TB, (const float*)f16, a16);
    PDL_LAUNCH((k_gemm2<16, 32, true, true>), tileBlocks, TB,
               (const float*)a16, W1, b1, (void*)c1h);

    // --- conv 2: 32 -> 64 (fp16 gather source, output fp16) ---
    PDL_LAUNCH(k_agg32h, wBlocks, TB, (const __half*)c1h, a32);
    PDL_LAUNCH((k_gemm2<32, 64, true, true>), tileBlocks, TB,
               (const float*)a32, W2, b2, (void*)c2h);

    // --- conv 3: 64 -> 128 (fp16 gather source, output fp32) ---
    PDL_LAUNCH(k_agg64h, wBlocks, TB, (const __half2*)c2h, a64);
    PDL_LAUNCH((k_gemm2<64, 128, false, false>), tileBlocks, TB,
               (const float*)a64, W3, b3, (void*)h128);

    // --- dense layers ---
    PDL_LAUNCH((k_gemm2<128, 64, false, false>), tileBlocks, TB,
               (const float*)h128, Wl1, bl1, (void*)h64);
    PDL_LAUNCH(k_l23, tileBlocks, TB,
               (const float*)h64, Wl2, bl2, Wl3, bl3, out);
}